// round 3
// baseline (speedup 1.0000x reference)
#include <cuda_runtime.h>
#include <math.h>

#define N_NODES   50000
#define N_EDGES   1600000
#define N_GRAPHS  256
#define DIM_IN    128
#define D1        100
#define D2        20
#define DIM_SELF  64

// ---------------- scratch (device globals; no allocation allowed) ----------
__device__ __align__(16) int   g_cnt[N_NODES];
__device__ __align__(16) int   g_rowptr[N_NODES + 1];
__device__ __align__(16) int   g_cursor[N_NODES];
__device__ __align__(16) int   g_csr[N_EDGES];
__device__ __align__(16) float g_p1[N_NODES * D1];   // feat @ W1
__device__ __align__(16) float g_h1[N_NODES * D1];   // relu(agg(p1)+b1)
__device__ __align__(16) float g_p2[N_NODES * D2];   // h1 @ W2
__device__ __align__(16) float g_h2[N_NODES * D2];   // relu(agg(p2)+b2)
__device__ __align__(16) float g_hg[N_GRAPHS * D2];
__device__ __align__(16) int   g_gcnt[N_GRAPHS];

// ---------------- zero per-call state --------------------------------------
__global__ void k_zero() {
    int i = blockIdx.x * blockDim.x + threadIdx.x;
    if (i < N_NODES) g_cnt[i] = 0;
    if (i < N_GRAPHS * D2) g_hg[i] = 0.f;
    if (i < N_GRAPHS) g_gcnt[i] = 0;
}

// ---------------- CSR build -------------------------------------------------
__global__ void k_count(const int* __restrict__ dst) {
    int e = blockIdx.x * blockDim.x + threadIdx.x;
    if (e < N_EDGES) atomicAdd(&g_cnt[dst[e]], 1);
}

// single-block exclusive scan of g_cnt -> g_rowptr / g_cursor
__global__ void k_scan() {
    __shared__ int ss[1024];
    int t = threadIdx.x;
    const int CH = (N_NODES + 1023) / 1024;   // 49
    int base = t * CH;
    int lim  = min(base + CH, N_NODES);
    int s = 0;
    for (int i = base; i < lim; i++) s += g_cnt[i];
    ss[t] = s;
    __syncthreads();
    for (int off = 1; off < 1024; off <<= 1) {
        int v = (t >= off) ? ss[t - off] : 0;
        __syncthreads();
        ss[t] += v;
        __syncthreads();
    }
    int run = (t == 0) ? 0 : ss[t - 1];
    for (int i = base; i < lim; i++) {
        g_rowptr[i] = run;
        g_cursor[i] = run;
        run += g_cnt[i];
    }
    if (t == 0) g_rowptr[N_NODES] = ss[1023];
}

__global__ void k_fill(const int* __restrict__ src, const int* __restrict__ dst) {
    int e = blockIdx.x * blockDim.x + threadIdx.x;
    if (e < N_EDGES) {
        int d = dst[e];
        int pos = atomicAdd(&g_cursor[d], 1);
        g_csr[pos] = src[e];
    }
}

// ---------------- GEMM1: p1 = feat @ W1  (50000x128 @ 128x100) -------------
// block: 256 threads, 10 rows per block; thread (r, cq) -> 4 cols cq*4..cq*4+3
__global__ void k_gemm1(const float* __restrict__ feat, const float* __restrict__ W1) {
    __shared__ __align__(16) float w1s[64 * D1];   // 25.6 KB (k-chunk of 64)
    __shared__ float fs[10 * 132];                 // padded feat tile
    int t  = threadIdx.x;
    int r0 = blockIdx.x * 10;

    for (int i = t; i < 10 * DIM_IN; i += 256) {
        int r = i >> 7, k = i & 127;
        fs[r * 132 + k] = feat[(r0 + r) * DIM_IN + k];
    }
    int  r  = t / 25, cq = t % 25;
    bool act = (t < 250);
    float a0 = 0.f, a1 = 0.f, a2 = 0.f, a3 = 0.f;

    for (int kc = 0; kc < DIM_IN; kc += 64) {
        __syncthreads();
        for (int i = t; i < 64 * D1; i += 256) w1s[i] = W1[kc * D1 + i];
        __syncthreads();
        if (act) {
            #pragma unroll 16
            for (int k = 0; k < 64; k++) {
                float a = fs[r * 132 + kc + k];
                float4 w = *(const float4*)&w1s[k * D1 + cq * 4];
                a0 += a * w.x; a1 += a * w.y; a2 += a * w.z; a3 += a * w.w;
            }
        }
    }
    if (act)
        *(float4*)&g_p1[(r0 + r) * D1 + cq * 4] = make_float4(a0, a1, a2, a3);
}

// ---------------- Aggregation layer 1 (dim 100, warp per node) --------------
__global__ void k_agg1(const float* __restrict__ b1) {
    int gw   = (blockIdx.x * blockDim.x + threadIdx.x) >> 5;
    int lane = threadIdx.x & 31;
    if (gw >= N_NODES) return;
    int start = g_rowptr[gw], end = g_rowptr[gw + 1];
    int deg = end - start;
    float a0 = 0.f, a1 = 0.f, a2 = 0.f, a3 = 0.f;
    for (int eb = start; eb < end; eb += 32) {
        int n = min(32, end - eb);
        int s = (lane < n) ? g_csr[eb + lane] : 0;
        for (int j = 0; j < n; j++) {
            int sj = __shfl_sync(0xffffffffu, s, j);
            const float* row = g_p1 + (size_t)sj * D1;
            a0 += row[lane];
            a1 += row[lane + 32];
            a2 += row[lane + 64];
            if (lane < 4) a3 += row[lane + 96];
        }
    }
    if (deg > 0) {
        float inv = 1.0f / (float)deg;
        a0 *= inv; a1 *= inv; a2 *= inv; a3 *= inv;
    } else {
        const float* row = g_p1 + (size_t)gw * D1;
        a0 = row[lane]; a1 = row[lane + 32]; a2 = row[lane + 64];
        a3 = (lane < 4) ? row[lane + 96] : 0.f;
    }
    float* out = g_h1 + (size_t)gw * D1;
    out[lane]      = fmaxf(a0 + b1[lane],      0.f);
    out[lane + 32] = fmaxf(a1 + b1[lane + 32], 0.f);
    out[lane + 64] = fmaxf(a2 + b1[lane + 64], 0.f);
    if (lane < 4) out[lane + 96] = fmaxf(a3 + b1[lane + 96], 0.f);
}

// ---------------- GEMM2: p2 = h1 @ W2  (50000x100 @ 100x20) ----------------
// block: 256 threads, 50 rows per block; thread (r, cq) -> 4 cols
__global__ void k_gemm2(const float* __restrict__ W2) {
    __shared__ __align__(16) float w2s[D1 * D2];   // 8 KB
    __shared__ float hs[50 * 104];                 // 20.8 KB padded
    int t  = threadIdx.x;
    int r0 = blockIdx.x * 50;
    for (int i = t; i < D1 * D2; i += 256) w2s[i] = W2[i];
    for (int i = t; i < 50 * D1; i += 256) {
        int r = i / D1, k = i % D1;
        hs[r * 104 + k] = g_h1[(size_t)(r0 + r) * D1 + k];
    }
    __syncthreads();
    if (t < 250) {
        int r = t / 5, cq = t % 5;
        float a0 = 0.f, a1 = 0.f, a2 = 0.f, a3 = 0.f;
        #pragma unroll 10
        for (int k = 0; k < D1; k++) {
            float a = hs[r * 104 + k];
            float4 w = *(const float4*)&w2s[k * D2 + cq * 4];
            a0 += a * w.x; a1 += a * w.y; a2 += a * w.z; a3 += a * w.w;
        }
        *(float4*)&g_p2[(size_t)(r0 + r) * D2 + cq * 4] = make_float4(a0, a1, a2, a3);
    }
}

// ---------------- Aggregation layer 2 (dim 20, warp per node) ---------------
__global__ void k_agg2(const float* __restrict__ b2) {
    int gw   = (blockIdx.x * blockDim.x + threadIdx.x) >> 5;
    int lane = threadIdx.x & 31;
    if (gw >= N_NODES) return;
    int start = g_rowptr[gw], end = g_rowptr[gw + 1];
    int deg = end - start;
    float a = 0.f;
    for (int eb = start; eb < end; eb += 32) {
        int n = min(32, end - eb);
        int s = (lane < n) ? g_csr[eb + lane] : 0;
        for (int j = 0; j < n; j++) {
            int sj = __shfl_sync(0xffffffffu, s, j);
            if (lane < D2) a += g_p2[(size_t)sj * D2 + lane];
        }
    }
    if (lane < D2) {
        float v = (deg > 0) ? a / (float)deg : g_p2[(size_t)gw * D2 + lane];
        g_h2[(size_t)gw * D2 + lane] = fmaxf(v + b2[lane], 0.f);
    }
}

// ---------------- per-graph mean pool ---------------------------------------
__global__ void k_pool(const int* __restrict__ gid) {
    int i = blockIdx.x * blockDim.x + threadIdx.x;
    if (i >= N_NODES * D2) return;
    int nd = i / D2, f = i - nd * D2;
    int g = gid[nd];
    atomicAdd(&g_hg[g * D2 + f], g_h2[i]);
    if (f == 0) atomicAdd(&g_gcnt[g], 1);
}

// ---------------- gate + MLP decoder (256 graphs, 1 block) ------------------
__global__ void k_final(const float* __restrict__ self_feat,
                        const float* __restrict__ Wp,  const float* __restrict__ bp,
                        const float* __restrict__ Wf1, const float* __restrict__ bf1,
                        const float* __restrict__ Wf2, const float* __restrict__ bf2,
                        float* __restrict__ out) {
    __shared__ float swp[DIM_SELF * D2];
    __shared__ float sbp[D2], swf1[D2 * 10], sbf1[10], swf2[10], sbf2;
    int t = threadIdx.x;
    for (int i = t; i < DIM_SELF * D2; i += 256) swp[i] = Wp[i];
    for (int i = t; i < D2 * 10; i += 256) swf1[i] = Wf1[i];
    if (t < D2) sbp[t] = bp[t];
    if (t < 10) { sbf1[t] = bf1[t]; swf2[t] = Wf2[t]; }
    if (t == 0) sbf2 = bf2[0];
    __syncthreads();

    int g = t;               // 256 threads == 256 graphs
    float hg[D2], z[D2];
    int c = g_gcnt[g];
    float invc = 1.0f / (float)max(c, 1);
    #pragma unroll
    for (int j = 0; j < D2; j++) { hg[j] = g_hg[g * D2 + j] * invc; z[j] = sbp[j]; }
    for (int i = 0; i < DIM_SELF; i++) {
        float sv = self_feat[g * DIM_SELF + i];
        #pragma unroll
        for (int j = 0; j < D2; j++) z[j] += sv * swp[i * D2 + j];
    }
    float m[10];
    #pragma unroll
    for (int o = 0; o < 10; o++) m[o] = sbf1[o];
    #pragma unroll
    for (int j = 0; j < D2; j++) {
        float p    = hg[j] * z[j];
        float gate = 1.0f / (1.0f + expf(-p));
        float f    = gate * hg[j] + (1.0f - gate) * z[j];
        #pragma unroll
        for (int o = 0; o < 10; o++) m[o] += f * swf1[j * 10 + o];
    }
    float o0 = sbf2;
    #pragma unroll
    for (int o = 0; o < 10; o++) o0 += fmaxf(m[o], 0.f) * swf2[o];
    out[g] = o0;
}

// ---------------- launch -----------------------------------------------------
extern "C" void kernel_launch(void* const* d_in, const int* in_sizes, int n_in,
                              void* d_out, int out_size) {
    const float* feat      = (const float*)d_in[0];
    const int*   src       = (const int*)  d_in[1];
    const int*   dst       = (const int*)  d_in[2];
    const int*   gid       = (const int*)  d_in[3];
    const float* self_feat = (const float*)d_in[4];
    const float* W1  = (const float*)d_in[5];
    const float* b1  = (const float*)d_in[6];
    const float* W2  = (const float*)d_in[7];
    const float* b2  = (const float*)d_in[8];
    const float* Wp  = (const float*)d_in[9];
    const float* bp  = (const float*)d_in[10];
    const float* Wf1 = (const float*)d_in[11];
    const float* bf1 = (const float*)d_in[12];
    const float* Wf2 = (const float*)d_in[13];
    const float* bf2 = (const float*)d_in[14];
    float* out = (float*)d_out;

    k_zero <<<(N_NODES + 255) / 256, 256>>>();
    k_count<<<(N_EDGES + 255) / 256, 256>>>(dst);
    k_scan <<<1, 1024>>>();
    k_fill <<<(N_EDGES + 255) / 256, 256>>>(src, dst);
    k_gemm1<<<N_NODES / 10, 256>>>(feat, W1);
    k_agg1 <<<(N_NODES + 7) / 8, 256>>>(b1);
    k_gemm2<<<N_NODES / 50, 256>>>(W2);
    k_agg2 <<<(N_NODES + 7) / 8, 256>>>(b2);
    k_pool <<<(N_NODES * D2 + 255) / 256, 256>>>(gid);
    k_final<<<1, 256>>>(self_feat, Wp, bp, Wf1, bf1, Wf2, bf2, out);
}

// round 7
// speedup vs baseline: 1.3632x; 1.3632x over previous
#include <cuda_runtime.h>
#include <cuda_fp16.h>
#include <mma.h>
#include <math.h>

using namespace nvcuda;

#define N_NODES   50000
#define N_EDGES   1600000
#define N_GRAPHS  256
#define DIM_IN    128
#define D1        100
#define D2        20
#define DIM_SELF  64

#define P1_LD2    64          // p1 row stride in half2 units (128 halfs = 256B, aligned)
#define P2_LD     32          // p2 row stride in floats (128B aligned)
#define W1_LD     112         // padded W1 cols (halfs) for wmma B tile

// ---------------- scratch (device globals; no allocation allowed) -----------
__device__ __align__(16) int     g_cnt[N_NODES];
__device__ __align__(16) int     g_rowptr[N_NODES + 1];
__device__ __align__(16) int     g_posn[N_EDGES];
__device__ __align__(16) int     g_csr[N_EDGES];
__device__ __align__(16) __half2 g_p1h[N_NODES * P1_LD2];   // feat @ W1 (fp16, padded rows)
__device__ __align__(16) float   g_h1[N_NODES * D1];        // relu(agg(p1)+b1) fp32
__device__ __align__(16) float   g_p2[N_NODES * P2_LD];     // h1 @ W2 (padded rows)
__device__ __align__(16) float   g_hg[N_GRAPHS * D2];
__device__ __align__(16) int     g_gcnt[N_GRAPHS];

// ---------------- zero per-call state ---------------------------------------
__global__ void k_zero() {
    int i = blockIdx.x * blockDim.x + threadIdx.x;
    if (i < N_NODES) g_cnt[i] = 0;
    if (i < N_GRAPHS * D2) g_hg[i] = 0.f;
    if (i < N_GRAPHS) g_gcnt[i] = 0;
}

// ---------------- CSR build: single atomic pass ------------------------------
// count + record intra-bucket position (the only atomic pass over edges)
__global__ void k_count(const int* __restrict__ dst) {
    int e4 = blockIdx.x * blockDim.x + threadIdx.x;
    if (e4 >= N_EDGES / 4) return;
    int4 d = ((const int4*)dst)[e4];
    int4 p;
    p.x = atomicAdd(&g_cnt[d.x], 1);
    p.y = atomicAdd(&g_cnt[d.y], 1);
    p.z = atomicAdd(&g_cnt[d.z], 1);
    p.w = atomicAdd(&g_cnt[d.w], 1);
    ((int4*)g_posn)[e4] = p;
}

// single-block exclusive scan of g_cnt -> g_rowptr
__global__ void k_scan() {
    __shared__ int ss[1024];
    int t = threadIdx.x;
    const int CH = (N_NODES + 1023) / 1024;   // 49
    int base = t * CH;
    int lim  = min(base + CH, N_NODES);
    int s = 0;
    for (int i = base; i < lim; i++) s += g_cnt[i];
    ss[t] = s;
    __syncthreads();
    for (int off = 1; off < 1024; off <<= 1) {
        int v = (t >= off) ? ss[t - off] : 0;
        __syncthreads();
        ss[t] += v;
        __syncthreads();
    }
    int run = (t == 0) ? 0 : ss[t - 1];
    for (int i = base; i < lim; i++) {
        g_rowptr[i] = run;
        run += g_cnt[i];
    }
    if (t == 0) g_rowptr[N_NODES] = ss[1023];
}

// atomic-free fill: slot known from recorded position
__global__ void k_fill(const int* __restrict__ src, const int* __restrict__ dst) {
    int e4 = blockIdx.x * blockDim.x + threadIdx.x;
    if (e4 >= N_EDGES / 4) return;
    int4 d = ((const int4*)dst)[e4];
    int4 p = ((const int4*)g_posn)[e4];
    int4 s = ((const int4*)src)[e4];
    g_csr[g_rowptr[d.x] + p.x] = s.x;
    g_csr[g_rowptr[d.y] + p.y] = s.y;
    g_csr[g_rowptr[d.z] + p.z] = s.z;
    g_csr[g_rowptr[d.w] + p.w] = s.w;
}

// ---------------- GEMM1: p1 = feat @ W1 via HMMA (fp16 in, fp32 accum) ------
// block = 256 threads (8 warps), 64 rows per block.
// warp w: row strip = w/2 (16 rows); even w -> col tiles 0..3, odd w -> 4..6.
__global__ void k_gemm1(const float* __restrict__ feat, const float* __restrict__ W1) {
    __shared__ __align__(16) unsigned char sm[45056];
    __half* Ah = (__half*)sm;                      // 64 x 128 halfs = 16384 B
    __half* Bh = (__half*)(sm + 16384);            // 128 x 112 halfs = 28672 B
    float*  Of = (float*)sm;                       // 64 x 112 floats = 28672 B (reuse)

    int t  = threadIdx.x;
    int r0 = blockIdx.x * 64;

    // stage W1 -> Bh (pad cols 100..111 with 0)
    for (int i = t; i < 128 * W1_LD; i += 256) {
        int k = i / W1_LD, c = i - k * W1_LD;
        Bh[i] = (c < D1) ? __float2half(W1[k * D1 + c]) : __float2half(0.f);
    }
    // stage feat tile -> Ah (guard rows)
    for (int i = t; i < 64 * DIM_IN; i += 256) {
        int r = i >> 7, k = i & 127;
        float v = (r0 + r < N_NODES) ? feat[(size_t)(r0 + r) * DIM_IN + k] : 0.f;
        Ah[i] = __float2half(v);
    }
    __syncthreads();

    int w     = t >> 5;
    int strip = w >> 1;
    int ct0   = (w & 1) ? 4 : 0;
    int nct   = (w & 1) ? 3 : 4;

    wmma::fragment<wmma::accumulator, 16, 16, 16, float> acc[4];
    for (int c = 0; c < 4; c++) wmma::fill_fragment(acc[c], 0.f);

    for (int k8 = 0; k8 < 8; k8++) {
        wmma::fragment<wmma::matrix_a, 16, 16, 16, __half, wmma::row_major> af;
        wmma::load_matrix_sync(af, Ah + strip * 16 * DIM_IN + k8 * 16, DIM_IN);
        for (int c = 0; c < nct; c++) {
            wmma::fragment<wmma::matrix_b, 16, 16, 16, __half, wmma::row_major> bf;
            wmma::load_matrix_sync(bf, Bh + (k8 * 16) * W1_LD + (ct0 + c) * 16, W1_LD);
            wmma::mma_sync(acc[c], af, bf, acc[c]);
        }
    }
    __syncthreads();   // done reading Ah/Bh; Of overlays them

    for (int c = 0; c < nct; c++)
        wmma::store_matrix_sync(Of + strip * 16 * W1_LD + (ct0 + c) * 16,
                                acc[c], W1_LD, wmma::mem_row_major);
    __syncthreads();

    // convert + store p1 as half2 (only cols 0..99)
    for (int i = t; i < 64 * 50; i += 256) {
        int r = i / 50, c2 = i - r * 50;
        if (r0 + r < N_NODES) {
            float fx = Of[r * W1_LD + 2 * c2];
            float fy = Of[r * W1_LD + 2 * c2 + 1];
            g_p1h[(size_t)(r0 + r) * P1_LD2 + c2] = __floats2half2_rn(fx, fy);
        }
    }
}

// ---------------- Aggregation layer 1 (fp16 gather, warp per node) ----------
// lane handles half2 {lane} (dims 2l,2l+1) and {32+lane} for lane<18.
__global__ void k_agg1(const float* __restrict__ b1) {
    int gw   = (blockIdx.x * blockDim.x + threadIdx.x) >> 5;
    int lane = threadIdx.x & 31;
    if (gw >= N_NODES) return;
    int start = g_rowptr[gw], end = g_rowptr[gw + 1];
    int deg = end - start;
    float a0x = 0.f, a0y = 0.f, a1x = 0.f, a1y = 0.f;
    for (int eb = start; eb < end; eb += 32) {
        int n = min(32, end - eb);
        int s = (lane < n) ? g_csr[eb + lane] : 0;
        for (int j = 0; j < n; j++) {
            int sj = __shfl_sync(0xffffffffu, s, j);
            const __half2* row = g_p1h + (size_t)sj * P1_LD2;
            float2 v0 = __half22float2(row[lane]);
            a0x += v0.x; a0y += v0.y;
            if (lane < 18) {
                float2 v1 = __half22float2(row[32 + lane]);
                a1x += v1.x; a1y += v1.y;
            }
        }
    }
    if (deg > 0) {
        float inv = 1.0f / (float)deg;
        a0x *= inv; a0y *= inv; a1x *= inv; a1y *= inv;
    } else {
        const __half2* row = g_p1h + (size_t)gw * P1_LD2;
        float2 v0 = __half22float2(row[lane]);
        a0x = v0.x; a0y = v0.y;
        if (lane < 18) {
            float2 v1 = __half22float2(row[32 + lane]);
            a1x = v1.x; a1y = v1.y;
        }
    }
    const float2* b1v = (const float2*)b1;
    float2* out0 = (float2*)(g_h1 + (size_t)gw * D1);
    float2 bb = b1v[lane];
    out0[lane] = make_float2(fmaxf(a0x + bb.x, 0.f), fmaxf(a0y + bb.y, 0.f));
    if (lane < 18) {
        float2 bc = b1v[32 + lane];
        out0[32 + lane] = make_float2(fmaxf(a1x + bc.x, 0.f), fmaxf(a1y + bc.y, 0.f));
    }
}

// ---------------- GEMM2: p2 = h1 @ W2  (50000x100 @ 100x20, fp32) -----------
__global__ void k_gemm2(const float* __restrict__ W2) {
    __shared__ __align__(16) float w2s[D1 * D2];   // 8 KB
    __shared__ float hs[50 * 104];                 // padded
    int t  = threadIdx.x;
    int r0 = blockIdx.x * 50;
    for (int i = t; i < D1 * D2; i += 256) w2s[i] = W2[i];
    for (int i = t; i < 50 * D1; i += 256) {
        int r = i / D1, k = i - r * D1;
        hs[r * 104 + k] = g_h1[(size_t)(r0 + r) * D1 + k];
    }
    __syncthreads();
    if (t < 250) {
        int r = t / 5, cq = t - r * 5;
        float a0 = 0.f, a1 = 0.f, a2 = 0.f, a3 = 0.f;
        #pragma unroll 10
        for (int k = 0; k < D1; k++) {
            float a = hs[r * 104 + k];
            float4 w = *(const float4*)&w2s[k * D2 + cq * 4];
            a0 += a * w.x; a1 += a * w.y; a2 += a * w.z; a3 += a * w.w;
        }
        *(float4*)&g_p2[(size_t)(r0 + r) * P2_LD + cq * 4] = make_float4(a0, a1, a2, a3);
    }
}

// ---------------- Aggregation layer 2 + fused per-graph pool ----------------
__global__ void k_agg2pool(const float* __restrict__ b2, const int* __restrict__ gid) {
    int gw   = (blockIdx.x * blockDim.x + threadIdx.x) >> 5;
    int lane = threadIdx.x & 31;
    if (gw >= N_NODES) return;
    int start = g_rowptr[gw], end = g_rowptr[gw + 1];
    int deg = end - start;
    float a = 0.f;
    for (int eb = start; eb < end; eb += 32) {
        int n = min(32, end - eb);
        int s = (lane < n) ? g_csr[eb + lane] : 0;
        for (int j = 0; j < n; j++) {
            int sj = __shfl_sync(0xffffffffu, s, j);
            if (lane < D2) a += g_p2[(size_t)sj * P2_LD + lane];
        }
    }
    int g = gid[gw];
    if (lane < D2) {
        float v = (deg > 0) ? a / (float)deg : g_p2[(size_t)gw * P2_LD + lane];
        float h2v = fmaxf(v + b2[lane], 0.f);
        atomicAdd(&g_hg[g * D2 + lane], h2v);
    }
    if (lane == 0) atomicAdd(&g_gcnt[g], 1);
}

// ---------------- gate + MLP decoder (256 graphs, 1 block) ------------------
__global__ void k_final(const float* __restrict__ self_feat,
                        const float* __restrict__ Wp,  const float* __restrict__ bp,
                        const float* __restrict__ Wf1, const float* __restrict__ bf1,
                        const float* __restrict__ Wf2, const float* __restrict__ bf2,
                        float* __restrict__ out) {
    __shared__ float swp[DIM_SELF * D2];
    __shared__ float sbp[D2], swf1[D2 * 10], sbf1[10], swf2[10], sbf2;
    int t = threadIdx.x;
    for (int i = t; i < DIM_SELF * D2; i += 256) swp[i] = Wp[i];
    for (int i = t; i < D2 * 10; i += 256) swf1[i] = Wf1[i];
    if (t < D2) sbp[t] = bp[t];
    if (t < 10) { sbf1[t] = bf1[t]; swf2[t] = Wf2[t]; }
    if (t == 0) sbf2 = bf2[0];
    __syncthreads();

    int g = t;
    float hg[D2], z[D2];
    int c = g_gcnt[g];
    float invc = 1.0f / (float)max(c, 1);
    #pragma unroll
    for (int j = 0; j < D2; j++) { hg[j] = g_hg[g * D2 + j] * invc; z[j] = sbp[j]; }
    for (int i = 0; i < DIM_SELF; i++) {
        float sv = self_feat[g * DIM_SELF + i];
        #pragma unroll
        for (int j = 0; j < D2; j++) z[j] += sv * swp[i * D2 + j];
    }
    float m[10];
    #pragma unroll
    for (int o = 0; o < 10; o++) m[o] = sbf1[o];
    #pragma unroll
    for (int j = 0; j < D2; j++) {
        float p    = hg[j] * z[j];
        float gate = 1.0f / (1.0f + expf(-p));
        float f    = gate * hg[j] + (1.0f - gate) * z[j];
        #pragma unroll
        for (int o = 0; o < 10; o++) m[o] += f * swf1[j * 10 + o];
    }
    float o0 = sbf2;
    #pragma unroll
    for (int o = 0; o < 10; o++) o0 += fmaxf(m[o], 0.f) * swf2[o];
    out[g] = o0;
}

// ---------------- launch -----------------------------------------------------
extern "C" void kernel_launch(void* const* d_in, const int* in_sizes, int n_in,
                              void* d_out, int out_size) {
    const float* feat      = (const float*)d_in[0];
    const int*   src       = (const int*)  d_in[1];
    const int*   dst       = (const int*)  d_in[2];
    const int*   gid       = (const int*)  d_in[3];
    const float* self_feat = (const float*)d_in[4];
    const float* W1  = (const float*)d_in[5];
    const float* b1  = (const float*)d_in[6];
    const float* W2  = (const float*)d_in[7];
    const float* b2  = (const float*)d_in[8];
    const float* Wp  = (const float*)d_in[9];
    const float* bp  = (const float*)d_in[10];
    const float* Wf1 = (const float*)d_in[11];
    const float* bf1 = (const float*)d_in[12];
    const float* Wf2 = (const float*)d_in[13];
    const float* bf2 = (const float*)d_in[14];
    float* out = (float*)d_out;

    k_zero    <<<(N_NODES + 255) / 256, 256>>>();
    k_count   <<<(N_EDGES / 4 + 255) / 256, 256>>>(dst);
    k_scan    <<<1, 1024>>>();
    k_fill    <<<(N_EDGES / 4 + 255) / 256, 256>>>(src, dst);
    k_gemm1   <<<(N_NODES + 63) / 64, 256>>>(feat, W1);
    k_agg1    <<<(N_NODES + 7) / 8, 256>>>(b1);
    k_gemm2   <<<N_NODES / 50, 256>>>(W2);
    k_agg2pool<<<(N_NODES + 7) / 8, 256>>>(b2, gid);
    k_final   <<<1, 256>>>(self_feat, Wp, bp, Wf1, bf1, Wf2, bf2, out);
}

// round 10
// speedup vs baseline: 1.6937x; 1.2424x over previous
#include <cuda_runtime.h>
#include <cuda_fp16.h>
#include <mma.h>
#include <math.h>

using namespace nvcuda;

#define N_NODES   50000
#define N_EDGES   1600000
#define N_GRAPHS  256
#define DIM_IN    128
#define D1        100
#define D2        20
#define DIM_SELF  64

#define P1_LD2    64          // p1 row stride in half2 (128 halfs = 256B aligned)
#define P2_LD2    16          // p2 row stride in half2 (32 halfs = 64B aligned)
#define W1_LD     112         // padded W1 cols (halfs) for wmma B tile

// ---------------- scratch (device globals; no allocation allowed) -----------
__device__ __align__(16) int     g_cnt[N_NODES];
__device__ __align__(16) int     g_rowptr[N_NODES + 1];
__device__ __align__(16) int     g_posn[N_EDGES];
__device__ __align__(16) int     g_csr[N_EDGES];
__device__ __align__(16) __half  g_w1h[128 * W1_LD];        // W1 pre-converted fp16
__device__ __align__(16) __half2 g_p1h[N_NODES * P1_LD2];   // feat @ W1 (fp16)
__device__ __align__(16) __half2 g_p2h[N_NODES * P2_LD2];   // h1 @ W2 (fp16)
__device__ __align__(16) float   g_hg[N_GRAPHS * D2];
__device__ __align__(16) int     g_gcnt[N_GRAPHS];

// ---------------- zero per-call state + one-time-per-call W1 convert --------
__global__ void k_zero(const float* __restrict__ W1) {
    int i = blockIdx.x * blockDim.x + threadIdx.x;
    if (i < N_NODES) g_cnt[i] = 0;
    if (i < N_GRAPHS * D2) g_hg[i] = 0.f;
    if (i < N_GRAPHS) g_gcnt[i] = 0;
    if (i < 128 * W1_LD) {
        int k = i / W1_LD, c = i - k * W1_LD;
        g_w1h[i] = (c < D1) ? __float2half(W1[k * D1 + c]) : __float2half(0.f);
    }
}

// ---------------- CSR build: single atomic pass ------------------------------
__global__ void k_count(const int* __restrict__ dst) {
    int e4 = blockIdx.x * blockDim.x + threadIdx.x;
    if (e4 >= N_EDGES / 4) return;
    int4 d = ((const int4*)dst)[e4];
    int4 p;
    p.x = atomicAdd(&g_cnt[d.x], 1);
    p.y = atomicAdd(&g_cnt[d.y], 1);
    p.z = atomicAdd(&g_cnt[d.z], 1);
    p.w = atomicAdd(&g_cnt[d.w], 1);
    ((int4*)g_posn)[e4] = p;
}

// single-block exclusive scan of g_cnt -> g_rowptr (int4-vectorized, CH=52)
__global__ void k_scan() {
    __shared__ int ss[1024];
    const int CH = 52;                       // 13 int4 per thread
    int t = threadIdx.x;
    int base = t * CH;
    int s = 0;
    if (base + CH <= N_NODES) {
        const int4* p = (const int4*)(g_cnt + base);
        #pragma unroll
        for (int i = 0; i < 13; i++) { int4 v = p[i]; s += v.x + v.y + v.z + v.w; }
    } else {
        for (int i = base; i < N_NODES; i++) s += g_cnt[i];
    }
    ss[t] = s;
    __syncthreads();
    for (int off = 1; off < 1024; off <<= 1) {
        int v = (t >= off) ? ss[t - off] : 0;
        __syncthreads();
        ss[t] += v;
        __syncthreads();
    }
    int run = (t == 0) ? 0 : ss[t - 1];
    if (base + CH <= N_NODES) {
        const int4* p = (const int4*)(g_cnt + base);
        int4* q = (int4*)(g_rowptr + base);
        #pragma unroll
        for (int i = 0; i < 13; i++) {
            int4 v = p[i];
            int4 o;
            o.x = run; run += v.x;
            o.y = run; run += v.y;
            o.z = run; run += v.z;
            o.w = run; run += v.w;
            q[i] = o;
        }
    } else {
        for (int i = base; i < N_NODES; i++) { g_rowptr[i] = run; run += g_cnt[i]; }
    }
    if (t == 0) g_rowptr[N_NODES] = N_EDGES;   // total is a known constant
}

// atomic-free fill: slot known from recorded position
__global__ void k_fill(const int* __restrict__ src, const int* __restrict__ dst) {
    int e4 = blockIdx.x * blockDim.x + threadIdx.x;
    if (e4 >= N_EDGES / 4) return;
    int4 d = ((const int4*)dst)[e4];
    int4 p = ((const int4*)g_posn)[e4];
    int4 s = ((const int4*)src)[e4];
    g_csr[g_rowptr[d.x] + p.x] = s.x;
    g_csr[g_rowptr[d.y] + p.y] = s.y;
    g_csr[g_rowptr[d.z] + p.z] = s.z;
    g_csr[g_rowptr[d.w] + p.w] = s.w;
}

// ---------------- GEMM1: p1 = feat @ W1 via HMMA ----------------------------
__global__ void k_gemm1(const float* __restrict__ feat) {
    __shared__ __align__(16) unsigned char sm[45056];
    __half* Ah = (__half*)sm;                      // 64 x 128 halfs = 16384 B
    __half* Bh = (__half*)(sm + 16384);            // 128 x 112 halfs = 28672 B
    float*  Of = (float*)sm;                       // 64 x 112 floats (overlay)

    int t  = threadIdx.x;
    int r0 = blockIdx.x * 64;

    // stage pre-converted W1 (int4 copies, no conversion)
    {
        const int4* w4 = (const int4*)g_w1h;
        int4* b4 = (int4*)Bh;
        #pragma unroll
        for (int i = t; i < 1792; i += 256) b4[i] = w4[i];
    }
    // stage + convert feat tile (float4 granularity)
    {
        __half2* a2 = (__half2*)Ah;
        for (int i = t; i < 64 * 32; i += 256) {
            int r = i >> 5, q = i & 31;
            float4 f = (r0 + r < N_NODES)
                     ? ((const float4*)feat)[(size_t)(r0 + r) * 32 + q]
                     : make_float4(0.f, 0.f, 0.f, 0.f);
            a2[r * 64 + 2 * q]     = __floats2half2_rn(f.x, f.y);
            a2[r * 64 + 2 * q + 1] = __floats2half2_rn(f.z, f.w);
        }
    }
    __syncthreads();

    int w     = t >> 5;
    int strip = w >> 1;
    int ct0   = (w & 1) ? 4 : 0;
    int nct   = (w & 1) ? 3 : 4;

    wmma::fragment<wmma::accumulator, 16, 16, 16, float> acc[4];
    for (int c = 0; c < 4; c++) wmma::fill_fragment(acc[c], 0.f);

    for (int k8 = 0; k8 < 8; k8++) {
        wmma::fragment<wmma::matrix_a, 16, 16, 16, __half, wmma::row_major> af;
        wmma::load_matrix_sync(af, Ah + strip * 16 * DIM_IN + k8 * 16, DIM_IN);
        for (int c = 0; c < nct; c++) {
            wmma::fragment<wmma::matrix_b, 16, 16, 16, __half, wmma::row_major> bf;
            wmma::load_matrix_sync(bf, Bh + (k8 * 16) * W1_LD + (ct0 + c) * 16, W1_LD);
            wmma::mma_sync(acc[c], af, bf, acc[c]);
        }
    }
    __syncthreads();

    for (int c = 0; c < nct; c++)
        wmma::store_matrix_sync(Of + strip * 16 * W1_LD + (ct0 + c) * 16,
                                acc[c], W1_LD, wmma::mem_row_major);
    __syncthreads();

    for (int i = t; i < 64 * 50; i += 256) {
        int r = i / 50, c2 = i - r * 50;
        if (r0 + r < N_NODES) {
            float fx = Of[r * W1_LD + 2 * c2];
            float fy = Of[r * W1_LD + 2 * c2 + 1];
            g_p1h[(size_t)(r0 + r) * P1_LD2 + c2] = __floats2half2_rn(fx, fy);
        }
    }
}

// ---------------- Fused: aggregation-1 + relu + GEMM2 -----------------------
// 8 warps, 1 node per warp; h1 row lands in smem; lanes 0..19 then do the
// 100x20 projection against smem W2 and write p2 (fp16).
__global__ void k_agg1g2(const float* __restrict__ b1, const float* __restrict__ W2) {
    __shared__ float h1s[8][104];
    __shared__ float w2s[D1 * D2];     // 8000 B
    int t = threadIdx.x, w = t >> 5, lane = t & 31;

    for (int i = t; i < D1 * D2; i += 256) w2s[i] = W2[i];

    int gw = blockIdx.x * 8 + w;
    if (gw < N_NODES) {
        int start = g_rowptr[gw], end = g_rowptr[gw + 1];
        int deg = end - start;
        float a0x = 0.f, a0y = 0.f, a1x = 0.f, a1y = 0.f;

        int nfull = deg & ~31;
        for (int eb = start; eb < start + nfull; eb += 32) {
            int s = g_csr[eb + lane];
            #pragma unroll
            for (int j = 0; j < 32; j++) {
                int sj = __shfl_sync(0xffffffffu, s, j);
                const __half2* row = g_p1h + (size_t)sj * P1_LD2;
                float2 v0 = __half22float2(row[lane]);
                a0x += v0.x; a0y += v0.y;
                if (lane < 18) {
                    float2 v1 = __half22float2(row[32 + lane]);
                    a1x += v1.x; a1y += v1.y;
                }
            }
        }
        int rem = deg - nfull;
        if (rem) {
            int s = (lane < rem) ? g_csr[start + nfull + lane] : 0;
            for (int j = 0; j < rem; j++) {
                int sj = __shfl_sync(0xffffffffu, s, j);
                const __half2* row = g_p1h + (size_t)sj * P1_LD2;
                float2 v0 = __half22float2(row[lane]);
                a0x += v0.x; a0y += v0.y;
                if (lane < 18) {
                    float2 v1 = __half22float2(row[32 + lane]);
                    a1x += v1.x; a1y += v1.y;
                }
            }
        }
        if (deg > 0) {
            float inv = 1.0f / (float)deg;
            a0x *= inv; a0y *= inv; a1x *= inv; a1y *= inv;
        } else {
            const __half2* row = g_p1h + (size_t)gw * P1_LD2;
            float2 v0 = __half22float2(row[lane]);
            a0x = v0.x; a0y = v0.y;
            if (lane < 18) {
                float2 v1 = __half22float2(row[32 + lane]);
                a1x = v1.x; a1y = v1.y;
            }
        }
        const float2* b1v = (const float2*)b1;
        float2 bb = b1v[lane];
        ((float2*)h1s[w])[lane] = make_float2(fmaxf(a0x + bb.x, 0.f),
                                              fmaxf(a0y + bb.y, 0.f));
        if (lane < 18) {
            float2 bc = b1v[32 + lane];
            ((float2*)h1s[w])[32 + lane] = make_float2(fmaxf(a1x + bc.x, 0.f),
                                                       fmaxf(a1y + bc.y, 0.f));
        }
    }
    __syncthreads();

    // GEMM2: p2[gw][c] = sum_k h1s[w][k] * W2[k][c], c = lane < 20
    if (gw < N_NODES) {
        float acc = 0.f;
        if (lane < D2) {
            #pragma unroll
            for (int k = 0; k < D1; k++)
                acc += h1s[w][k] * w2s[k * D2 + lane];
        }
        float hi = __shfl_down_sync(0xffffffffu, acc, 1);
        if (lane < D2 && (lane & 1) == 0)
            g_p2h[(size_t)gw * P2_LD2 + (lane >> 1)] = __floats2half2_rn(acc, hi);
    }
}

// ---------------- Aggregation layer 2 (fp16, 2 edges/iter) + pool -----------
__global__ void k_agg2pool(const float* __restrict__ b2, const int* __restrict__ gid) {
    int gw   = (blockIdx.x * blockDim.x + threadIdx.x) >> 5;
    int lane = threadIdx.x & 31;
    if (gw >= N_NODES) return;
    int start = g_rowptr[gw], end = g_rowptr[gw + 1];
    int deg = end - start;
    int half = lane >> 4;       // 0: even edges, 1: odd edges
    int idx  = lane & 15;       // half2 index within row (<10 active)
    float ax = 0.f, ay = 0.f;
    for (int eb = start; eb < end; eb += 32) {
        int n = min(32, end - eb);
        int s = (lane < n) ? g_csr[eb + lane] : 0;
        for (int j = 0; j < n; j += 2) {
            int je = j + half;
            int sj = __shfl_sync(0xffffffffu, s, je);
            if (idx < 10 && je < n) {
                float2 v = __half22float2(g_p2h[(size_t)sj * P2_LD2 + idx]);
                ax += v.x; ay += v.y;
            }
        }
    }
    // combine even/odd partial sums
    ax += __shfl_xor_sync(0xffffffffu, ax, 16);
    ay += __shfl_xor_sync(0xffffffffu, ay, 16);

    int g = gid[gw];
    if (lane < 10) {
        float vx, vy;
        if (deg > 0) {
            float inv = 1.0f / (float)deg;
            vx = ax * inv; vy = ay * inv;
        } else {
            float2 v = __half22float2(g_p2h[(size_t)gw * P2_LD2 + lane]);
            vx = v.x; vy = v.y;
        }
        const float2* b2v = (const float2*)b2;
        float2 bb = b2v[lane];
        atomicAdd(&g_hg[g * D2 + 2 * lane],     fmaxf(vx + bb.x, 0.f));
        atomicAdd(&g_hg[g * D2 + 2 * lane + 1], fmaxf(vy + bb.y, 0.f));
    }
    if (lane == 0) atomicAdd(&g_gcnt[g], 1);
}

// ---------------- gate + MLP decoder (256 graphs, 1 block) ------------------
__global__ void k_final(const float* __restrict__ self_feat,
                        const float* __restrict__ Wp,  const float* __restrict__ bp,
                        const float* __restrict__ Wf1, const float* __restrict__ bf1,
                        const float* __restrict__ Wf2, const float* __restrict__ bf2,
                        float* __restrict__ out) {
    __shared__ float swp[DIM_SELF * D2];
    __shared__ float sbp[D2], swf1[D2 * 10], sbf1[10], swf2[10], sbf2;
    int t = threadIdx.x;
    for (int i = t; i < DIM_SELF * D2; i += 256) swp[i] = Wp[i];
    for (int i = t; i < D2 * 10; i += 256) swf1[i] = Wf1[i];
    if (t < D2) sbp[t] = bp[t];
    if (t < 10) { sbf1[t] = bf1[t]; swf2[t] = Wf2[t]; }
    if (t == 0) sbf2 = bf2[0];
    __syncthreads();

    int g = t;
    float hg[D2], z[D2];
    int c = g_gcnt[g];
    float invc = 1.0f / (float)max(c, 1);
    #pragma unroll
    for (int j = 0; j < D2; j++) { hg[j] = g_hg[g * D2 + j] * invc; z[j] = sbp[j]; }
    for (int i = 0; i < DIM_SELF; i++) {
        float sv = self_feat[g * DIM_SELF + i];
        #pragma unroll
        for (int j = 0; j < D2; j++) z[j] += sv * swp[i * D2 + j];
    }
    float m[10];
    #pragma unroll
    for (int o = 0; o < 10; o++) m[o] = sbf1[o];
    #pragma unroll
    for (int j = 0; j < D2; j++) {
        float p    = hg[j] * z[j];
        float gate = 1.0f / (1.0f + expf(-p));
        float f    = gate * hg[j] + (1.0f - gate) * z[j];
        #pragma unroll
        for (int o = 0; o < 10; o++) m[o] += f * swf1[j * 10 + o];
    }
    float o0 = sbf2;
    #pragma unroll
    for (int o = 0; o < 10; o++) o0 += fmaxf(m[o], 0.f) * swf2[o];
    out[g] = o0;
}

// ---------------- launch -----------------------------------------------------
extern "C" void kernel_launch(void* const* d_in, const int* in_sizes, int n_in,
                              void* d_out, int out_size) {
    const float* feat      = (const float*)d_in[0];
    const int*   src       = (const int*)  d_in[1];
    const int*   dst       = (const int*)  d_in[2];
    const int*   gid       = (const int*)  d_in[3];
    const float* self_feat = (const float*)d_in[4];
    const float* W1  = (const float*)d_in[5];
    const float* b1  = (const float*)d_in[6];
    const float* W2  = (const float*)d_in[7];
    const float* b2  = (const float*)d_in[8];
    const float* Wp  = (const float*)d_in[9];
    const float* bp  = (const float*)d_in[10];
    const float* Wf1 = (const float*)d_in[11];
    const float* bf1 = (const float*)d_in[12];
    const float* Wf2 = (const float*)d_in[13];
    const float* bf2 = (const float*)d_in[14];
    float* out = (float*)d_out;

    k_zero    <<<(N_NODES + 255) / 256, 256>>>(W1);
    k_count   <<<(N_EDGES / 4 + 255) / 256, 256>>>(dst);
    k_scan    <<<1, 1024>>>();
    k_fill    <<<(N_EDGES / 4 + 255) / 256, 256>>>(src, dst);
    k_gemm1   <<<(N_NODES + 63) / 64, 256>>>(feat);
    k_agg1g2  <<<(N_NODES + 7) / 8, 256>>>(b1, W2);
    k_agg2pool<<<(N_NODES + 7) / 8, 256>>>(b2, gid);
    k_final   <<<1, 256>>>(self_feat, Wp, bp, Wf1, bf1, Wf2, bf2, out);
}